// round 9
// baseline (speedup 1.0000x reference)
#include <cuda_runtime.h>
#include <cuda_bf16.h>
#include <cuda_fp16.h>
#include <math.h>
#include <stdint.h>

// Problem constants
#define E_    16
#define H_    1024
#define D_    2048
#define R_    16
#define T_    1024
#define NSLOT 2048
#define LIMIT_   7.0f
#define ACT_ALPHA_ 1.702f

// ---------------- device scratch ------------------------------------------
__device__ int   d_count[E_];
__device__ int   d_off[E_];
__device__ int   d_slot_token[NSLOT];
__device__ int   d_slot_expert[NSLOT];
__device__ float d_slot_w[NSLOT];
__device__ float d_r1[NSLOT * R_];
__device__ float d_g [(size_t)NSLOT * 1024];
__device__ float d_r2[NSLOT * R_];

// ---------------- routing ---------------------------------------------------
__global__ void route_kernel(const int* __restrict__ ridx,
                             const float* __restrict__ rw) {
    __shared__ int cnt[E_], cur[E_], soff[E_ + 1];
    int t = threadIdx.x;
    if (t < E_) { cnt[t] = 0; cur[t] = 0; }
    __syncthreads();
    for (int i = t; i < NSLOT; i += blockDim.x)
        atomicAdd(&cnt[ridx[i]], 1);
    __syncthreads();
    if (t == 0) {
        int s = 0;
        for (int e = 0; e < E_; e++) { soff[e] = s; s += cnt[e]; }
        soff[E_] = s;
    }
    __syncthreads();
    for (int i = t; i < NSLOT; i += blockDim.x) {
        int e = ridx[i];
        int slot = soff[e] + atomicAdd(&cur[e], 1);
        d_slot_token[slot]  = i >> 1;
        d_slot_expert[slot] = e;
        d_slot_w[slot]      = rw[i];
    }
    if (t < E_) { d_count[t] = cnt[t]; d_off[t] = soff[t]; }
}

// ---------------- zero output (atomically accumulated later) -----------------
__global__ void zero_out_kernel(float* __restrict__ out) {
    int i = blockIdx.x * 256 + threadIdx.x;
    *(float4*)&out[(size_t)i * 4] = make_float4(0.f, 0.f, 0.f, 0.f);
}

// ---------------- LoRA rank projection --------------------------------------
template <bool STAGE1>
__global__ void lora_r_kernel(const float* __restrict__ xsrc,
                              const float* __restrict__ A) {  // [E,1024,16]
    int slot = blockIdx.x;
    int e    = d_slot_expert[slot];
    const float* Ae   = A + (size_t)e * 1024 * R_;
    const float* srow = STAGE1 ? (xsrc + (size_t)d_slot_token[slot] * 1024)
                               : (d_g + (size_t)slot * 1024);
    float* rout = STAGE1 ? d_r1 : d_r2;
    int tid = threadIdx.x;  // 256
    float acc[R_];
#pragma unroll
    for (int j = 0; j < R_; j++) acc[j] = 0.f;
    for (int k = tid; k < 1024; k += 256) {
        float a = srow[k];
        const float4* ar = (const float4*)(Ae + k * R_);
#pragma unroll
        for (int q = 0; q < 4; q++) {
            float4 v = __ldg(ar + q);
            acc[q * 4]     += a * v.x;
            acc[q * 4 + 1] += a * v.y;
            acc[q * 4 + 2] += a * v.z;
            acc[q * 4 + 3] += a * v.w;
        }
    }
#pragma unroll
    for (int o = 16; o > 0; o >>= 1)
#pragma unroll
        for (int j = 0; j < R_; j++)
            acc[j] += __shfl_down_sync(0xffffffffu, acc[j], o);
    __shared__ float wr[8][R_];
    int lane = tid & 31, w = tid >> 5;
    if (lane == 0)
#pragma unroll
        for (int j = 0; j < R_; j++) wr[w][j] = acc[j];
    __syncthreads();
    if (tid < R_) {
        float s = 0.f;
#pragma unroll
        for (int ww = 0; ww < 8; ww++) s += wr[ww][tid];
        rout[slot * R_ + tid] = s;  // SCALING = 16/16 = 1
    }
}

// ================= mma.sync / cp.async helpers ==============================
__device__ __forceinline__ uint32_t smem_u32(const void* p) {
    return (uint32_t)__cvta_generic_to_shared(p);
}
__device__ __forceinline__ void ldsm4(uint32_t* r, uint32_t addr) {
    asm volatile("ldmatrix.sync.aligned.m8n8.x4.shared.b16 {%0,%1,%2,%3}, [%4];"
                 : "=r"(r[0]), "=r"(r[1]), "=r"(r[2]), "=r"(r[3]) : "r"(addr));
}
__device__ __forceinline__ void ldsm4t(uint32_t* r, uint32_t addr) {
    asm volatile("ldmatrix.sync.aligned.m8n8.x4.trans.shared.b16 {%0,%1,%2,%3}, [%4];"
                 : "=r"(r[0]), "=r"(r[1]), "=r"(r[2]), "=r"(r[3]) : "r"(addr));
}
__device__ __forceinline__ void mma16816f(float* d, const uint32_t* a,
                                          const uint32_t* b) {
    asm volatile(
        "mma.sync.aligned.m16n8k16.row.col.f32.f16.f16.f32 "
        "{%0,%1,%2,%3}, {%4,%5,%6,%7}, {%8,%9}, {%0,%1,%2,%3};"
        : "+f"(d[0]), "+f"(d[1]), "+f"(d[2]), "+f"(d[3])
        : "r"(a[0]), "r"(a[1]), "r"(a[2]), "r"(a[3]), "r"(b[0]), "r"(b[1]));
}
__device__ __forceinline__ uint4 cvt8_f16(const float4 a, const float4 b) {
    uint4 r;
    asm("cvt.rn.f16x2.f32 %0, %1, %2;" : "=r"(r.x) : "f"(a.y), "f"(a.x));
    asm("cvt.rn.f16x2.f32 %0, %1, %2;" : "=r"(r.y) : "f"(a.w), "f"(a.z));
    asm("cvt.rn.f16x2.f32 %0, %1, %2;" : "=r"(r.z) : "f"(b.y), "f"(b.x));
    asm("cvt.rn.f16x2.f32 %0, %1, %2;" : "=r"(r.w) : "f"(b.w), "f"(b.z));
    return r;
}
__device__ __forceinline__ void cp_async16(uint32_t saddr, const void* gaddr) {
    asm volatile("cp.async.cg.shared.global [%0], [%1], 16;"
                 :: "r"(saddr), "l"(gaddr));
}
__device__ __forceinline__ void cp_commit() {
    asm volatile("cp.async.commit_group;");
}
template <int N>
__device__ __forceinline__ void cp_wait() {
    asm volatile("cp.async.wait_group %0;" :: "n"(N));
}

// SMEM layout (static, 45056 B):
//   B raw fp32: 3 stages x 8192  @ 0        (16 k-rows x 512B)
//   A f16:      2 stages x 6144  @ 24576    (128 rows x 48B: 32B data + pad)
//   B f16:      2 stages x 4096  @ 36864    (16 k-rows x 256B, XOR swizzle)
#define SM_RAWB(s) ((s) * 8192)
#define SM_A(s)    (24576 + (s) * 6144)
#define SM_B(s)    (36864 + (s) * 4096)

// ================= grouped GEMM: cp.async W pipeline + fp16 mma.sync ========
// STAGE1: d_g = act(x[tok] @ Wgu + r1 @ LBgu + bias)    Ncols=2048
// STAGE2: out += w * (d_g @ Wdn + r2 @ LBdn + bias)     Ncols=1024, atomics
// CTA tile 128x128, BK=16; K-loop: 64 main iters + 1 LoRA iter (rank 16).
template <bool STAGE1>
__global__ __launch_bounds__(256, 2)
void moe_mma_kernel(const float* __restrict__ xsrc,
                    const float* __restrict__ W,     // [E,1024,Ncols]
                    const float* __restrict__ LB,    // [E,16,Ncols]
                    const float* __restrict__ bias,  // [E,Ncols]
                    float* __restrict__ Out,
                    int Ncols) {
    const int e  = blockIdx.z;
    const int ne = d_count[e];
    const int off = d_off[e];
    const int n0  = blockIdx.x * 128;
    const float* Rsrc = STAGE1 ? d_r1 : d_r2;
    float* Outp = STAGE1 ? d_g : Out;

    __shared__ __align__(16) char sm[45056];
    const uint32_t sb = smem_u32(sm);

    const int tid  = threadIdx.x;
    const int lane = tid & 31;
    const int wid  = tid >> 5;
    const int wm   = wid >> 2;       // 0..1 (64 rows)
    const int wn   = wid & 3;        // 0..3 (32 cols)

    // per-thread load mapping
    const int arow = tid >> 1;            // A: 2 threads/row
    const int ac0  = (tid & 1) * 8;       // 8-float half of 16-float chunk
    const int krow = tid >> 4;            // B: 0..15
    const int bc   = tid & 15;            // 8-float chunk within 128-float row
    const int braw_ofs = krow * 512 + bc * 32;
    const int bofs_sw  = krow * 256 + ((bc ^ (krow & 7)) << 4);
    const float* bptr  = W  + ((size_t)e * 1024 + krow) * Ncols + n0 + bc * 8;
    const float* lbptr = LB + ((size_t)e * R_   + krow) * Ncols + n0 + bc * 8;

    for (int mb = blockIdx.y; mb * 128 < ne; mb += 4) {
        const int m0 = mb * 128;
        const bool avalid = (m0 + arow) < ne;
        const int aslot = off + m0 + arow;
        const float* aptr = nullptr;
        const float* rptr = nullptr;
        if (avalid) {
            aptr = STAGE1 ? (xsrc + (size_t)d_slot_token[aslot] * 1024)
                          : (d_g + (size_t)aslot * 1024);
            rptr = Rsrc + (size_t)aslot * R_;
        }

        float acc[4][4][4];
#pragma unroll
        for (int i = 0; i < 4; i++)
#pragma unroll
            for (int j = 0; j < 4; j++)
#pragma unroll
                for (int q = 0; q < 4; q++) acc[i][j][q] = 0.f;

        float4 pa0, pa1;
        auto loadA = [&](int t) {
            if (avalid) {
                const float* p = (t < 64) ? (aptr + t * 16 + ac0) : (rptr + ac0);
                pa0 = __ldg((const float4*)p);
                pa1 = __ldg((const float4*)(p + 4));
            } else { pa0 = pa1 = make_float4(0.f, 0.f, 0.f, 0.f); }
        };
        auto issueB = [&](int t) {                 // raw fp32 W tile via cp.async
            if (t <= 64) {
                const float* src = (t < 64) ? (bptr + (size_t)t * 16 * Ncols) : lbptr;
                uint32_t dst = sb + SM_RAWB(t % 3) + braw_ofs;
                cp_async16(dst,      src);
                cp_async16(dst + 16, src + 4);
            }
            cp_commit();                           // empty group ok past end
        };
        auto storeA = [&](int t) {                 // regs -> f16 A[t&1]
            *(uint4*)(sm + SM_A(t & 1) + arow * 48 + (tid & 1) * 16) =
                cvt8_f16(pa0, pa1);
        };
        auto convB = [&](int t) {                  // raw[t%3] -> f16 B[t&1]
            const char* rp = sm + SM_RAWB(t % 3) + braw_ofs;
            float4 b0 = *(const float4*)rp;
            float4 b1 = *(const float4*)(rp + 16);
            *(uint4*)(sm + SM_B(t & 1) + bofs_sw) = cvt8_f16(b0, b1);
        };

        // ---- prologue: B tiles 0,1 in flight; A tile 0 in regs ----
        loadA(0);
        issueB(0);
        issueB(1);
        cp_wait<1>();          // B tile 0 arrived (this thread)
        __syncthreads();       // all threads' tile-0 copies visible
        storeA(0);
        convB(0);

        for (int it = 0; it <= 64; ++it) {
            __syncthreads();               // f16[it&1] stores visible to all
            issueB(it + 2);
            if (it < 64) loadA(it + 1);    // A prefetch (L2) hides under MMAs

            // ---- MMA on f16[it&1] ----
            uint32_t bh[2][4];
            {
                int k = ((lane >> 3) & 1) * 8 + (lane & 7);
                int cbase = (lane >> 4);
#pragma unroll
                for (int g = 0; g < 2; g++) {
                    int c = wn * 4 + g * 2 + cbase;
                    ldsm4t(bh[g], sb + SM_B(it & 1) + k * 256 + ((c ^ (k & 7)) << 4));
                }
            }
#pragma unroll
            for (int mt = 0; mt < 4; mt++) {
                uint32_t ah[4];
                int m = wm * 64 + mt * 16 + (lane & 15);
                ldsm4(ah, sb + SM_A(it & 1) + m * 48 + (lane >> 4) * 16);
#pragma unroll
                for (int nt = 0; nt < 4; nt++)
                    mma16816f(acc[mt][nt], ah, &bh[nt >> 1][(nt & 1) * 2]);
            }

            if (it < 64) {
                cp_wait<1>();              // B tile it+1 arrived (this thread)
                __syncthreads();           // cross-thread arrival + MMA done
                storeA(it + 1);
                convB(it + 1);
            }
        }

        // ---- epilogue ----
        const float* be = bias + (size_t)e * Ncols + n0;
        float bb[4][2];
#pragma unroll
        for (int nt = 0; nt < 4; nt++) {
            int col = wn * 32 + nt * 8 + (lane & 3) * 2;
            bb[nt][0] = __ldg(be + col);
            bb[nt][1] = __ldg(be + col + 1);
        }
#pragma unroll
        for (int mt = 0; mt < 4; mt++) {
            int rbase = m0 + wm * 64 + mt * 16 + (lane >> 2);
#pragma unroll
            for (int half = 0; half < 2; half++) {
                int r = rbase + half * 8;
                if (r >= ne) continue;
                int slot = off + r;
                if (STAGE1) {
                    size_t orow = (size_t)slot * 1024 + (n0 >> 1);
#pragma unroll
                    for (int nt = 0; nt < 4; nt++) {
                        float c0 = acc[mt][nt][half * 2]     + bb[nt][0];
                        float c1 = acc[mt][nt][half * 2 + 1] + bb[nt][1];
                        int col = wn * 32 + nt * 8 + (lane & 3) * 2;
                        float gate = fminf(c0, LIMIT_);
                        float up   = fminf(fmaxf(c1, -LIMIT_), LIMIT_);
                        float glu  = gate / (1.f + expf(-ACT_ALPHA_ * gate));
                        Outp[orow + (col >> 1)] = (up + 1.f) * glu;
                    }
                } else {
                    float wgt = d_slot_w[slot];
                    size_t orow = (size_t)d_slot_token[slot] * 1024 + n0;
#pragma unroll
                    for (int nt = 0; nt < 4; nt++) {
                        float c0 = acc[mt][nt][half * 2]     + bb[nt][0];
                        float c1 = acc[mt][nt][half * 2 + 1] + bb[nt][1];
                        int col = wn * 32 + nt * 8 + (lane & 3) * 2;
                        atomicAdd(Outp + orow + col,     wgt * c0);
                        atomicAdd(Outp + orow + col + 1, wgt * c1);
                    }
                }
            }
        }
        __syncthreads();  // smem safe for next m-block
    }
}

// ---------------- launch: kernel launches ONLY ------------------------------
extern "C" void kernel_launch(void* const* d_in, const int* in_sizes, int n_in,
                              void* d_out, int out_size) {
    const float* x     = (const float*)d_in[0];
    const int*   ridx  = (const int*)  d_in[1];
    const float* rw    = (const float*)d_in[2];
    const float* w_gu  = (const float*)d_in[3];
    const float* b_gu  = (const float*)d_in[4];
    const float* w_dn  = (const float*)d_in[5];
    const float* b_dn  = (const float*)d_in[6];
    const float* la_gu = (const float*)d_in[7];
    const float* lb_gu = (const float*)d_in[8];
    const float* la_dn = (const float*)d_in[9];
    const float* lb_dn = (const float*)d_in[10];
    float* out = (float*)d_out;

    route_kernel<<<1, 1024>>>(ridx, rw);
    zero_out_kernel<<<T_ * H_ / 1024, 256>>>(out);

    lora_r_kernel<true ><<<NSLOT, 256>>>(x, la_gu);
    moe_mma_kernel<true ><<<dim3(D_ / 128, 4, E_), 256>>>(x, w_gu, lb_gu, b_gu,
                                                          nullptr, D_);
    lora_r_kernel<false><<<NSLOT, 256>>>(x, la_dn);
    moe_mma_kernel<false><<<dim3(H_ / 128, 4, E_), 256>>>(x, w_dn, lb_dn, b_dn,
                                                          out, H_);
}

// round 10
// speedup vs baseline: 1.0045x; 1.0045x over previous
#include <cuda_runtime.h>
#include <cuda_bf16.h>
#include <cuda_fp16.h>
#include <math.h>
#include <stdint.h>

// Problem constants
#define E_    16
#define H_    1024
#define D_    2048
#define R_    16
#define T_    1024
#define NSLOT 2048
#define LIMIT_   7.0f
#define ACT_ALPHA_ 1.702f

// ---------------- device scratch ------------------------------------------
__device__ int   d_count[E_];
__device__ int   d_off[E_];
__device__ int   d_slot_token[NSLOT];
__device__ int   d_slot_expert[NSLOT];
__device__ float d_slot_w[NSLOT];
__device__ float d_r1[NSLOT * R_];
__device__ float d_g [(size_t)NSLOT * 1024];
__device__ float d_r2[NSLOT * R_];

// ---------------- routing ---------------------------------------------------
__global__ void route_kernel(const int* __restrict__ ridx,
                             const float* __restrict__ rw) {
    __shared__ int cnt[E_], cur[E_], soff[E_ + 1];
    int t = threadIdx.x;
    if (t < E_) { cnt[t] = 0; cur[t] = 0; }
    __syncthreads();
    for (int i = t; i < NSLOT; i += blockDim.x)
        atomicAdd(&cnt[ridx[i]], 1);
    __syncthreads();
    if (t == 0) {
        int s = 0;
        for (int e = 0; e < E_; e++) { soff[e] = s; s += cnt[e]; }
        soff[E_] = s;
    }
    __syncthreads();
    for (int i = t; i < NSLOT; i += blockDim.x) {
        int e = ridx[i];
        int slot = soff[e] + atomicAdd(&cur[e], 1);
        d_slot_token[slot]  = i >> 1;
        d_slot_expert[slot] = e;
        d_slot_w[slot]      = rw[i];
    }
    if (t < E_) { d_count[t] = cnt[t]; d_off[t] = soff[t]; }
}

// ---------------- zero output (atomically accumulated later) -----------------
__global__ void zero_out_kernel(float* __restrict__ out) {
    int i = blockIdx.x * 256 + threadIdx.x;
    *(float4*)&out[(size_t)i * 4] = make_float4(0.f, 0.f, 0.f, 0.f);
}

// ---------------- LoRA rank projection --------------------------------------
template <bool STAGE1>
__global__ void lora_r_kernel(const float* __restrict__ xsrc,
                              const float* __restrict__ A) {  // [E,1024,16]
    int slot = blockIdx.x;
    int e    = d_slot_expert[slot];
    const float* Ae   = A + (size_t)e * 1024 * R_;
    const float* srow = STAGE1 ? (xsrc + (size_t)d_slot_token[slot] * 1024)
                               : (d_g + (size_t)slot * 1024);
    float* rout = STAGE1 ? d_r1 : d_r2;
    int tid = threadIdx.x;  // 256
    float acc[R_];
#pragma unroll
    for (int j = 0; j < R_; j++) acc[j] = 0.f;
    for (int k = tid; k < 1024; k += 256) {
        float a = srow[k];
        const float4* ar = (const float4*)(Ae + k * R_);
#pragma unroll
        for (int q = 0; q < 4; q++) {
            float4 v = __ldg(ar + q);
            acc[q * 4]     += a * v.x;
            acc[q * 4 + 1] += a * v.y;
            acc[q * 4 + 2] += a * v.z;
            acc[q * 4 + 3] += a * v.w;
        }
    }
#pragma unroll
    for (int o = 16; o > 0; o >>= 1)
#pragma unroll
        for (int j = 0; j < R_; j++)
            acc[j] += __shfl_down_sync(0xffffffffu, acc[j], o);
    __shared__ float wr[8][R_];
    int lane = tid & 31, w = tid >> 5;
    if (lane == 0)
#pragma unroll
        for (int j = 0; j < R_; j++) wr[w][j] = acc[j];
    __syncthreads();
    if (tid < R_) {
        float s = 0.f;
#pragma unroll
        for (int ww = 0; ww < 8; ww++) s += wr[ww][tid];
        rout[slot * R_ + tid] = s;  // SCALING = 16/16 = 1
    }
}

// ================= mma.sync helpers =========================================
__device__ __forceinline__ uint32_t smem_u32(const void* p) {
    return (uint32_t)__cvta_generic_to_shared(p);
}
__device__ __forceinline__ void ldsm4(uint32_t* r, uint32_t addr) {
    asm volatile("ldmatrix.sync.aligned.m8n8.x4.shared.b16 {%0,%1,%2,%3}, [%4];"
                 : "=r"(r[0]), "=r"(r[1]), "=r"(r[2]), "=r"(r[3]) : "r"(addr));
}
__device__ __forceinline__ void ldsm4t(uint32_t* r, uint32_t addr) {
    asm volatile("ldmatrix.sync.aligned.m8n8.x4.trans.shared.b16 {%0,%1,%2,%3}, [%4];"
                 : "=r"(r[0]), "=r"(r[1]), "=r"(r[2]), "=r"(r[3]) : "r"(addr));
}
__device__ __forceinline__ void mma16816f(float* d, const uint32_t* a,
                                          const uint32_t* b) {
    asm volatile(
        "mma.sync.aligned.m16n8k16.row.col.f32.f16.f16.f32 "
        "{%0,%1,%2,%3}, {%4,%5,%6,%7}, {%8,%9}, {%0,%1,%2,%3};"
        : "+f"(d[0]), "+f"(d[1]), "+f"(d[2]), "+f"(d[3])
        : "r"(a[0]), "r"(a[1]), "r"(a[2]), "r"(a[3]), "r"(b[0]), "r"(b[1]));
}
__device__ __forceinline__ uint4 cvt8_f16(const float4 a, const float4 b) {
    uint4 r;
    asm("cvt.rn.f16x2.f32 %0, %1, %2;" : "=r"(r.x) : "f"(a.y), "f"(a.x));
    asm("cvt.rn.f16x2.f32 %0, %1, %2;" : "=r"(r.y) : "f"(a.w), "f"(a.z));
    asm("cvt.rn.f16x2.f32 %0, %1, %2;" : "=r"(r.z) : "f"(b.y), "f"(b.x));
    asm("cvt.rn.f16x2.f32 %0, %1, %2;" : "=r"(r.w) : "f"(b.w), "f"(b.z));
    return r;
}
__device__ __forceinline__ uint2 cvt4_f16(const float4 a) {
    uint2 r;
    asm("cvt.rn.f16x2.f32 %0, %1, %2;" : "=r"(r.x) : "f"(a.y), "f"(a.x));
    asm("cvt.rn.f16x2.f32 %0, %1, %2;" : "=r"(r.y) : "f"(a.w), "f"(a.z));
    return r;
}

// SMEM layout (static, 16384 B), double-buffered f16:
//   A[stage]: 128 rows x 48B (32B data + 16B pad)     @ s*6144
//   B[stage]: 16 k-rows x 128B (XOR-swizzled chunks)  @ 12288 + s*2048
#define SM_A(s) ((s) * 6144)
#define SM_B(s) (12288 + (s) * 2048)

// ================= grouped GEMM via mma.sync fp16 ===========================
// STAGE1: d_g = act(x[tok] @ Wgu + r1 @ LBgu + bias)    Ncols=2048
// STAGE2: out += w * (d_g @ Wdn + r2 @ LBdn + bias)     Ncols=1024, atomics
// CTA tile 128x64, 8 warps (4m x 2n), warp tile 32x32, BK=16.
// K-loop: 64 main iters + 1 LoRA iter (rank 16). B prefetch depth 2.
template <bool STAGE1>
__global__ __launch_bounds__(256, 3)
void moe_mma_kernel(const float* __restrict__ xsrc,
                    const float* __restrict__ W,     // [E,1024,Ncols]
                    const float* __restrict__ LB,    // [E,16,Ncols]
                    const float* __restrict__ bias,  // [E,Ncols]
                    float* __restrict__ Out,
                    int Ncols) {
    const int e  = blockIdx.z;
    const int ne = d_count[e];
    const int off = d_off[e];
    const int n0  = blockIdx.x * 64;
    const float* Rsrc = STAGE1 ? d_r1 : d_r2;
    float* Outp = STAGE1 ? d_g : Out;

    __shared__ __align__(16) char sm[16384];
    const uint32_t sb = smem_u32(sm);

    const int tid  = threadIdx.x;
    const int lane = tid & 31;
    const int wid  = tid >> 5;
    const int wm   = wid >> 1;       // 0..3 (32 rows each)
    const int wn   = wid & 1;        // 0..1 (32 cols each)

    // per-thread load mapping
    const int arow = tid >> 1;            // A: 2 threads/row
    const int ac0  = (tid & 1) * 8;       // 8-float half of 16-float chunk
    const int krow = tid >> 4;            // B: 0..15
    const int bgrp = tid & 15;            // 4-float group within 64-float row
    const int bofs_sw = krow * 128 + (((bgrp >> 1) ^ (krow & 7)) << 4)
                      + (bgrp & 1) * 8;
    const float* bptr  = W  + ((size_t)e * 1024 + krow) * Ncols + n0 + bgrp * 4;
    const float* lbptr = LB + ((size_t)e * R_   + krow) * Ncols + n0 + bgrp * 4;

    for (int mb = blockIdx.y; mb * 128 < ne; mb += 4) {
        const int m0 = mb * 128;
        const bool avalid = (m0 + arow) < ne;
        const int aslot = off + m0 + arow;
        const float* aptr = nullptr;
        const float* rptr = nullptr;
        if (avalid) {
            aptr = STAGE1 ? (xsrc + (size_t)d_slot_token[aslot] * 1024)
                          : (d_g + (size_t)aslot * 1024);
            rptr = Rsrc + (size_t)aslot * R_;
        }

        float acc[2][4][4];
#pragma unroll
        for (int i = 0; i < 2; i++)
#pragma unroll
            for (int j = 0; j < 4; j++)
#pragma unroll
                for (int q = 0; q < 4; q++) acc[i][j][q] = 0.f;

        float4 pa0, pa1;            // A tile (depth 1)
        float4 pbr[2];              // B tiles (depth 2 ring)
        auto loadA = [&](int t) {
            if (avalid) {
                const float* p = (t < 64) ? (aptr + t * 16 + ac0) : (rptr + ac0);
                pa0 = __ldg((const float4*)p);
                pa1 = __ldg((const float4*)(p + 4));
            } else { pa0 = pa1 = make_float4(0.f, 0.f, 0.f, 0.f); }
        };
        auto loadB = [&](int t, int slot) {
            if (t < 64)
                pbr[slot] = __ldg((const float4*)(bptr + (size_t)t * 16 * Ncols));
            else if (t == 64)
                pbr[slot] = __ldg((const float4*)lbptr);
        };
        auto storeTile = [&](int s, int bslot) {
            *(uint4*)(sm + SM_A(s) + arow * 48 + (tid & 1) * 16) =
                cvt8_f16(pa0, pa1);
            *(uint2*)(sm + SM_B(s) + bofs_sw) = cvt4_f16(pbr[bslot]);
        };

        // ---- prologue: B tiles 0,1 issued; A tile 0 issued ----
        loadA(0);
        loadB(0, 0);
        loadB(1, 1);
        storeTile(0, 0);           // waits on tile-0 arrivals
        __syncthreads();

        int s = 0;
        for (int it = 0; it <= 64; ++it) {
            loadB(it + 2, it & 1);         // 2-iter slack on W stream
            if (it < 64) loadA(it + 1);    // 1-iter slack (L2)

            // ---- B fragments: 2x ldmatrix.x4.trans (16 n-cols each) ----
            uint32_t bh[2][4];
            {
                int k = ((lane >> 3) & 1) * 8 + (lane & 7);
                int cbase = (lane >> 4);
#pragma unroll
                for (int g = 0; g < 2; g++) {
                    int c = wn * 4 + g * 2 + cbase;
                    ldsm4t(bh[g], sb + SM_B(s) + k * 128 + ((c ^ (k & 7)) << 4));
                }
            }
            // ---- A fragments + MMAs ----
#pragma unroll
            for (int mt = 0; mt < 2; mt++) {
                uint32_t ah[4];
                int m = wm * 32 + mt * 16 + (lane & 15);
                ldsm4(ah, sb + SM_A(s) + m * 48 + (lane >> 4) * 16);
#pragma unroll
                for (int nt = 0; nt < 4; nt++)
                    mma16816f(acc[mt][nt], ah, &bh[nt >> 1][(nt & 1) * 2]);
            }
            if (it < 64) storeTile(s ^ 1, (it + 1) & 1);
            __syncthreads();
            s ^= 1;
        }

        // ---- epilogue ----
        const float* be = bias + (size_t)e * Ncols + n0;
        float bb[4][2];
#pragma unroll
        for (int nt = 0; nt < 4; nt++) {
            int col = wn * 32 + nt * 8 + (lane & 3) * 2;
            bb[nt][0] = __ldg(be + col);
            bb[nt][1] = __ldg(be + col + 1);
        }
#pragma unroll
        for (int mt = 0; mt < 2; mt++) {
            int rbase = m0 + wm * 32 + mt * 16 + (lane >> 2);
#pragma unroll
            for (int half = 0; half < 2; half++) {
                int r = rbase + half * 8;
                if (r >= ne) continue;
                int slot = off + r;
                if (STAGE1) {
                    size_t orow = (size_t)slot * 1024 + (n0 >> 1);
#pragma unroll
                    for (int nt = 0; nt < 4; nt++) {
                        float c0 = acc[mt][nt][half * 2]     + bb[nt][0];
                        float c1 = acc[mt][nt][half * 2 + 1] + bb[nt][1];
                        int col = wn * 32 + nt * 8 + (lane & 3) * 2;
                        float gate = fminf(c0, LIMIT_);
                        float up   = fminf(fmaxf(c1, -LIMIT_), LIMIT_);
                        float glu  = gate / (1.f + expf(-ACT_ALPHA_ * gate));
                        Outp[orow + (col >> 1)] = (up + 1.f) * glu;
                    }
                } else {
                    float wgt = d_slot_w[slot];
                    size_t orow = (size_t)d_slot_token[slot] * 1024 + n0;
#pragma unroll
                    for (int nt = 0; nt < 4; nt++) {
                        float c0 = acc[mt][nt][half * 2]     + bb[nt][0];
                        float c1 = acc[mt][nt][half * 2 + 1] + bb[nt][1];
                        int col = wn * 32 + nt * 8 + (lane & 3) * 2;
                        atomicAdd(Outp + orow + col,     wgt * c0);
                        atomicAdd(Outp + orow + col + 1, wgt * c1);
                    }
                }
            }
        }
        __syncthreads();  // smem safe for next m-block
    }
}

// ---------------- launch: kernel launches ONLY ------------------------------
extern "C" void kernel_launch(void* const* d_in, const int* in_sizes, int n_in,
                              void* d_out, int out_size) {
    const float* x     = (const float*)d_in[0];
    const int*   ridx  = (const int*)  d_in[1];
    const float* rw    = (const float*)d_in[2];
    const float* w_gu  = (const float*)d_in[3];
    const float* b_gu  = (const float*)d_in[4];
    const float* w_dn  = (const float*)d_in[5];
    const float* b_dn  = (const float*)d_in[6];
    const float* la_gu = (const float*)d_in[7];
    const float* lb_gu = (const float*)d_in[8];
    const float* la_dn = (const float*)d_in[9];
    const float* lb_dn = (const float*)d_in[10];
    float* out = (float*)d_out;

    route_kernel<<<1, 1024>>>(ridx, rw);
    zero_out_kernel<<<T_ * H_ / 1024, 256>>>(out);

    lora_r_kernel<true ><<<NSLOT, 256>>>(x, la_gu);
    moe_mma_kernel<true ><<<dim3(D_ / 64, 4, E_), 256>>>(x, w_gu, lb_gu, b_gu,
                                                         nullptr, D_);
    lora_r_kernel<false><<<NSLOT, 256>>>(x, la_dn);
    moe_mma_kernel<false><<<dim3(H_ / 64, 4, E_), 256>>>(x, w_dn, lb_dn, b_dn,
                                                         out, H_);
}

// round 11
// speedup vs baseline: 1.0522x; 1.0475x over previous
#include <cuda_runtime.h>
#include <cuda_bf16.h>
#include <cuda_fp16.h>
#include <math.h>
#include <stdint.h>

// Problem constants
#define E_    16
#define H_    1024
#define D_    2048
#define R_    16
#define T_    1024
#define NSLOT 2048
#define LIMIT_   7.0f
#define ACT_ALPHA_ 1.702f

// ---------------- device scratch ------------------------------------------
__device__ int   d_count[E_];
__device__ int   d_off[E_];
__device__ int   d_slot_token[NSLOT];
__device__ int   d_slot_expert[NSLOT];
__device__ float d_slot_w[NSLOT];
__device__ float d_r1[NSLOT * R_];
__device__ float d_g [(size_t)NSLOT * 1024];
__device__ float d_r2[NSLOT * R_];

// ---------------- routing ---------------------------------------------------
__global__ void route_kernel(const int* __restrict__ ridx,
                             const float* __restrict__ rw) {
    __shared__ int cnt[E_], cur[E_], soff[E_ + 1];
    int t = threadIdx.x;
    if (t < E_) { cnt[t] = 0; cur[t] = 0; }
    __syncthreads();
    for (int i = t; i < NSLOT; i += blockDim.x)
        atomicAdd(&cnt[ridx[i]], 1);
    __syncthreads();
    if (t == 0) {
        int s = 0;
        for (int e = 0; e < E_; e++) { soff[e] = s; s += cnt[e]; }
        soff[E_] = s;
    }
    __syncthreads();
    for (int i = t; i < NSLOT; i += blockDim.x) {
        int e = ridx[i];
        int slot = soff[e] + atomicAdd(&cur[e], 1);
        d_slot_token[slot]  = i >> 1;
        d_slot_expert[slot] = e;
        d_slot_w[slot]      = rw[i];
    }
    if (t < E_) { d_count[t] = cnt[t]; d_off[t] = soff[t]; }
}

// ---------------- zero output (atomically accumulated later) -----------------
__global__ void zero_out_kernel(float* __restrict__ out) {
    int i = blockIdx.x * 256 + threadIdx.x;
    *(float4*)&out[(size_t)i * 4] = make_float4(0.f, 0.f, 0.f, 0.f);
}

// ---------------- LoRA rank projection --------------------------------------
template <bool STAGE1>
__global__ void lora_r_kernel(const float* __restrict__ xsrc,
                              const float* __restrict__ A) {  // [E,1024,16]
    int slot = blockIdx.x;
    int e    = d_slot_expert[slot];
    const float* Ae   = A + (size_t)e * 1024 * R_;
    const float* srow = STAGE1 ? (xsrc + (size_t)d_slot_token[slot] * 1024)
                               : (d_g + (size_t)slot * 1024);
    float* rout = STAGE1 ? d_r1 : d_r2;
    int tid = threadIdx.x;  // 256
    float acc[R_];
#pragma unroll
    for (int j = 0; j < R_; j++) acc[j] = 0.f;
    for (int k = tid; k < 1024; k += 256) {
        float a = srow[k];
        const float4* ar = (const float4*)(Ae + k * R_);
#pragma unroll
        for (int q = 0; q < 4; q++) {
            float4 v = __ldg(ar + q);
            acc[q * 4]     += a * v.x;
            acc[q * 4 + 1] += a * v.y;
            acc[q * 4 + 2] += a * v.z;
            acc[q * 4 + 3] += a * v.w;
        }
    }
#pragma unroll
    for (int o = 16; o > 0; o >>= 1)
#pragma unroll
        for (int j = 0; j < R_; j++)
            acc[j] += __shfl_down_sync(0xffffffffu, acc[j], o);
    __shared__ float wr[8][R_];
    int lane = tid & 31, w = tid >> 5;
    if (lane == 0)
#pragma unroll
        for (int j = 0; j < R_; j++) wr[w][j] = acc[j];
    __syncthreads();
    if (tid < R_) {
        float s = 0.f;
#pragma unroll
        for (int ww = 0; ww < 8; ww++) s += wr[ww][tid];
        rout[slot * R_ + tid] = s;  // SCALING = 16/16 = 1
    }
}

// ================= mma.sync helpers =========================================
__device__ __forceinline__ uint32_t smem_u32(const void* p) {
    return (uint32_t)__cvta_generic_to_shared(p);
}
__device__ __forceinline__ void ldsm4(uint32_t* r, uint32_t addr) {
    asm volatile("ldmatrix.sync.aligned.m8n8.x4.shared.b16 {%0,%1,%2,%3}, [%4];"
                 : "=r"(r[0]), "=r"(r[1]), "=r"(r[2]), "=r"(r[3]) : "r"(addr));
}
__device__ __forceinline__ void ldsm4t(uint32_t* r, uint32_t addr) {
    asm volatile("ldmatrix.sync.aligned.m8n8.x4.trans.shared.b16 {%0,%1,%2,%3}, [%4];"
                 : "=r"(r[0]), "=r"(r[1]), "=r"(r[2]), "=r"(r[3]) : "r"(addr));
}
__device__ __forceinline__ void mma16816f(float* d, const uint32_t* a,
                                          const uint32_t* b) {
    asm volatile(
        "mma.sync.aligned.m16n8k16.row.col.f32.f16.f16.f32 "
        "{%0,%1,%2,%3}, {%4,%5,%6,%7}, {%8,%9}, {%0,%1,%2,%3};"
        : "+f"(d[0]), "+f"(d[1]), "+f"(d[2]), "+f"(d[3])
        : "r"(a[0]), "r"(a[1]), "r"(a[2]), "r"(a[3]), "r"(b[0]), "r"(b[1]));
}
__device__ __forceinline__ uint4 cvt8_f16(const float4 a, const float4 b) {
    uint4 r;
    asm("cvt.rn.f16x2.f32 %0, %1, %2;" : "=r"(r.x) : "f"(a.y), "f"(a.x));
    asm("cvt.rn.f16x2.f32 %0, %1, %2;" : "=r"(r.y) : "f"(a.w), "f"(a.z));
    asm("cvt.rn.f16x2.f32 %0, %1, %2;" : "=r"(r.z) : "f"(b.y), "f"(b.x));
    asm("cvt.rn.f16x2.f32 %0, %1, %2;" : "=r"(r.w) : "f"(b.w), "f"(b.z));
    return r;
}

// SMEM layout (static, 36864 B), double-buffered f16, BK=32:
//   A[stage]: 128 rows x 80B (64B data + 16B pad)     @ s*10240
//   B[stage]: 32 k-rows x 256B (XOR-swizzled chunks)  @ 20480 + s*8192
#define SM_A(s) ((s) * 10240)
#define SM_B(s) (20480 + (s) * 8192)

// ================= grouped GEMM via mma.sync fp16, BK=32 ====================
// STAGE1: d_g = act(x[tok] @ Wgu + r1 @ LBgu + bias)    Ncols=2048
// STAGE2: out += w * (d_g @ Wdn + r2 @ LBdn + bias)     Ncols=1024, atomics
// CTA tile 128x128, 8 warps (2m x 4n), warp tile 64x32.
// K-loop: 32 main iters + 1 zero-padded LoRA iter (rank 16 in low half).
template <bool STAGE1>
__global__ __launch_bounds__(256, 2)
void moe_mma_kernel(const float* __restrict__ xsrc,
                    const float* __restrict__ W,     // [E,1024,Ncols]
                    const float* __restrict__ LB,    // [E,16,Ncols]
                    const float* __restrict__ bias,  // [E,Ncols]
                    float* __restrict__ Out,
                    int Ncols) {
    const int e  = blockIdx.z;
    const int ne = d_count[e];
    const int off = d_off[e];
    const int n0  = blockIdx.x * 128;
    const float* Rsrc = STAGE1 ? d_r1 : d_r2;
    float* Outp = STAGE1 ? d_g : Out;

    __shared__ __align__(16) char sm[36864];
    const uint32_t sb = smem_u32(sm);

    const int tid  = threadIdx.x;
    const int lane = tid & 31;
    const int wid  = tid >> 5;
    const int wm   = wid >> 2;       // 0..1 (64 rows)
    const int wn   = wid & 3;        // 0..3 (32 cols)

    // per-thread load mapping (BK=32)
    const int arow = tid >> 1;            // A: 2 threads/row
    const int akh  = (tid & 1) * 16;      // 16-float k-half within 32-k chunk
    const int krow = tid >> 3;            // B: 0..31
    const int bc   = tid & 7;             // 16-float n-group within 128
    const float* bptr  = W  + ((size_t)e * 1024 + krow) * Ncols + n0 + bc * 16;
    const float* lbptr = LB + ((size_t)e * R_   + krow) * Ncols + n0 + bc * 16;

    for (int mb = blockIdx.y; mb * 128 < ne; mb += 4) {
        const int m0 = mb * 128;
        const bool avalid = (m0 + arow) < ne;
        const int aslot = off + m0 + arow;
        const float* aptr = nullptr;
        const float* rptr = nullptr;
        if (avalid) {
            aptr = STAGE1 ? (xsrc + (size_t)d_slot_token[aslot] * 1024)
                          : (d_g + (size_t)aslot * 1024);
            rptr = Rsrc + (size_t)aslot * R_;
        }

        float acc[4][4][4];
#pragma unroll
        for (int i = 0; i < 4; i++)
#pragma unroll
            for (int j = 0; j < 4; j++)
#pragma unroll
                for (int q = 0; q < 4; q++) acc[i][j][q] = 0.f;

        float4 pa[4], pb[4];
        auto loadA = [&](int t) {
            if (t > 32) return;
            if (avalid && (t < 32 || akh == 0)) {
                const float* p = (t < 32) ? (aptr + t * 32 + akh) : rptr;
#pragma unroll
                for (int q = 0; q < 4; q++) pa[q] = __ldg((const float4*)(p + q * 4));
            } else {
#pragma unroll
                for (int q = 0; q < 4; q++) pa[q] = make_float4(0.f, 0.f, 0.f, 0.f);
            }
        };
        auto loadB = [&](int t) {
            if (t > 32) return;
            if (t < 32) {
                const float* p = bptr + (size_t)t * 32 * Ncols;
#pragma unroll
                for (int q = 0; q < 4; q++) pb[q] = __ldg((const float4*)(p + q * 4));
            } else if (krow < R_) {
#pragma unroll
                for (int q = 0; q < 4; q++) pb[q] = __ldg((const float4*)(lbptr + q * 4));
            } else {
#pragma unroll
                for (int q = 0; q < 4; q++) pb[q] = make_float4(0.f, 0.f, 0.f, 0.f);
            }
        };
        auto storeTile = [&](int s) {
            // A: 32B (16 f16) at row*80 + khalf*32
            char* ap = sm + SM_A(s) + arow * 80 + (tid & 1) * 32;
            *(uint4*)ap        = cvt8_f16(pa[0], pa[1]);
            *(uint4*)(ap + 16) = cvt8_f16(pa[2], pa[3]);
            // B: two swizzled 16B chunks c0=2bc, c1=2bc+1 in 256B row
            char* bp = sm + SM_B(s) + krow * 256;
            int c0 = bc * 2, c1 = bc * 2 + 1, kx = krow & 7;
            *(uint4*)(bp + ((c0 ^ kx) << 4)) = cvt8_f16(pb[0], pb[1]);
            *(uint4*)(bp + ((c1 ^ kx) << 4)) = cvt8_f16(pb[2], pb[3]);
        };

        // ---- prologue ----
        loadA(0); loadB(0);
        storeTile(0);
        __syncthreads();

        int s = 0;
        for (int it = 0; it <= 32; ++it) {
            loadA(it + 1); loadB(it + 1);   // prefetch (hidden under MMAs)

#pragma unroll
            for (int kh = 0; kh < 2; kh++) {
                // B fragments for this 16-k half
                uint32_t bh[2][4];
                {
                    int k = ((lane >> 3) & 1) * 8 + (lane & 7);
                    int cbase = (lane >> 4);
#pragma unroll
                    for (int g = 0; g < 2; g++) {
                        int c = wn * 4 + g * 2 + cbase;
                        ldsm4t(bh[g], sb + SM_B(s) + (kh * 16 + k) * 256
                                     + ((c ^ (k & 7)) << 4));
                    }
                }
                // A fragments + MMAs
#pragma unroll
                for (int mt = 0; mt < 4; mt++) {
                    uint32_t ah[4];
                    int m = wm * 64 + mt * 16 + (lane & 15);
                    ldsm4(ah, sb + SM_A(s) + m * 80 + kh * 32 + (lane >> 4) * 16);
#pragma unroll
                    for (int nt = 0; nt < 4; nt++)
                        mma16816f(acc[mt][nt], ah, &bh[nt >> 1][(nt & 1) * 2]);
                }
            }
            if (it < 32) storeTile(s ^ 1);
            __syncthreads();
            s ^= 1;
        }

        // ---- epilogue ----
        const float* be = bias + (size_t)e * Ncols + n0;
        float bb[4][2];
#pragma unroll
        for (int nt = 0; nt < 4; nt++) {
            int col = wn * 32 + nt * 8 + (lane & 3) * 2;
            bb[nt][0] = __ldg(be + col);
            bb[nt][1] = __ldg(be + col + 1);
        }
#pragma unroll
        for (int mt = 0; mt < 4; mt++) {
            int rbase = m0 + wm * 64 + mt * 16 + (lane >> 2);
#pragma unroll
            for (int half = 0; half < 2; half++) {
                int r = rbase + half * 8;
                if (r >= ne) continue;
                int slot = off + r;
                if (STAGE1) {
                    size_t orow = (size_t)slot * 1024 + (n0 >> 1);
#pragma unroll
                    for (int nt = 0; nt < 4; nt++) {
                        float c0 = acc[mt][nt][half * 2]     + bb[nt][0];
                        float c1 = acc[mt][nt][half * 2 + 1] + bb[nt][1];
                        int col = wn * 32 + nt * 8 + (lane & 3) * 2;
                        float gate = fminf(c0, LIMIT_);
                        float up   = fminf(fmaxf(c1, -LIMIT_), LIMIT_);
                        float glu  = gate / (1.f + expf(-ACT_ALPHA_ * gate));
                        Outp[orow + (col >> 1)] = (up + 1.f) * glu;
                    }
                } else {
                    float wgt = d_slot_w[slot];
                    size_t orow = (size_t)d_slot_token[slot] * 1024 + n0;
#pragma unroll
                    for (int nt = 0; nt < 4; nt++) {
                        float c0 = acc[mt][nt][half * 2]     + bb[nt][0];
                        float c1 = acc[mt][nt][half * 2 + 1] + bb[nt][1];
                        int col = wn * 32 + nt * 8 + (lane & 3) * 2;
                        atomicAdd(Outp + orow + col,     wgt * c0);
                        atomicAdd(Outp + orow + col + 1, wgt * c1);
                    }
                }
            }
        }
        __syncthreads();  // smem safe for next m-block
    }
}

// ---------------- launch: kernel launches ONLY ------------------------------
extern "C" void kernel_launch(void* const* d_in, const int* in_sizes, int n_in,
                              void* d_out, int out_size) {
    const float* x     = (const float*)d_in[0];
    const int*   ridx  = (const int*)  d_in[1];
    const float* rw    = (const float*)d_in[2];
    const float* w_gu  = (const float*)d_in[3];
    const float* b_gu  = (const float*)d_in[4];
    const float* w_dn  = (const float*)d_in[5];
    const float* b_dn  = (const float*)d_in[6];
    const float* la_gu = (const float*)d_in[7];
    const float* lb_gu = (const float*)d_in[8];
    const float* la_dn = (const float*)d_in[9];
    const float* lb_dn = (const float*)d_in[10];
    float* out = (float*)d_out;

    route_kernel<<<1, 1024>>>(ridx, rw);
    zero_out_kernel<<<T_ * H_ / 1024, 256>>>(out);

    lora_r_kernel<true ><<<NSLOT, 256>>>(x, la_gu);
    moe_mma_kernel<true ><<<dim3(D_ / 128, 4, E_), 256>>>(x, w_gu, lb_gu, b_gu,
                                                          nullptr, D_);
    lora_r_kernel<false><<<NSLOT, 256>>>(x, la_dn);
    moe_mma_kernel<false><<<dim3(H_ / 128, 4, E_), 256>>>(x, w_dn, lb_dn, b_dn,
                                                          out, H_);
}

// round 14
// speedup vs baseline: 1.2020x; 1.1424x over previous
#include <cuda_runtime.h>
#include <cuda_bf16.h>
#include <cuda_fp16.h>
#include <math.h>
#include <stdint.h>

// Problem constants
#define E_    16
#define H_    1024
#define D_    2048
#define R_    16
#define T_    1024
#define NSLOT 2048
#define NPAD  (NSLOT + 128)
#define LIMIT_   7.0f
#define ACT_ALPHA_ 1.702f

// ---------------- device scratch (~9.1 MB total — proven-safe scale) --------
__device__ int    d_count[E_];
__device__ int    d_off[E_];
__device__ int    d_slot_token[NSLOT];
__device__ int    d_slot_expert[NSLOT];
__device__ float  d_slot_w[NSLOT];
__device__ __half d_xh[(size_t)NPAD * 1024];   // gathered x, f16
__device__ __half d_gh[(size_t)NPAD * 1024];   // glu out, f16
__device__ __half d_r1[(size_t)NPAD * R_];     // lora acts f16
__device__ __half d_r2[(size_t)NPAD * R_];

// ---------------- helpers ----------------------------------------------------
__device__ __forceinline__ uint32_t smem_u32(const void* p) {
    return (uint32_t)__cvta_generic_to_shared(p);
}
__device__ __forceinline__ uint2 cvt4h(const float4 a) {
    uint2 r;
    asm("cvt.rn.f16x2.f32 %0, %1, %2;" : "=r"(r.x) : "f"(a.y), "f"(a.x));
    asm("cvt.rn.f16x2.f32 %0, %1, %2;" : "=r"(r.y) : "f"(a.w), "f"(a.z));
    return r;
}
__device__ __forceinline__ uint4 cvt8_f16(const float4 a, const float4 b) {
    uint4 r;
    asm("cvt.rn.f16x2.f32 %0, %1, %2;" : "=r"(r.x) : "f"(a.y), "f"(a.x));
    asm("cvt.rn.f16x2.f32 %0, %1, %2;" : "=r"(r.y) : "f"(a.w), "f"(a.z));
    asm("cvt.rn.f16x2.f32 %0, %1, %2;" : "=r"(r.z) : "f"(b.y), "f"(b.x));
    asm("cvt.rn.f16x2.f32 %0, %1, %2;" : "=r"(r.w) : "f"(b.w), "f"(b.z));
    return r;
}
__device__ __forceinline__ void ldsm4(uint32_t* r, uint32_t addr) {
    asm volatile("ldmatrix.sync.aligned.m8n8.x4.shared.b16 {%0,%1,%2,%3}, [%4];"
                 : "=r"(r[0]), "=r"(r[1]), "=r"(r[2]), "=r"(r[3]) : "r"(addr));
}
__device__ __forceinline__ void ldsm4t(uint32_t* r, uint32_t addr) {
    asm volatile("ldmatrix.sync.aligned.m8n8.x4.trans.shared.b16 {%0,%1,%2,%3}, [%4];"
                 : "=r"(r[0]), "=r"(r[1]), "=r"(r[2]), "=r"(r[3]) : "r"(addr));
}
__device__ __forceinline__ void mma16816f(float* d, const uint32_t* a,
                                          const uint32_t* b) {
    asm volatile(
        "mma.sync.aligned.m16n8k16.row.col.f32.f16.f16.f32 "
        "{%0,%1,%2,%3}, {%4,%5,%6,%7}, {%8,%9}, {%0,%1,%2,%3};"
        : "+f"(d[0]), "+f"(d[1]), "+f"(d[2]), "+f"(d[3])
        : "r"(a[0]), "r"(a[1]), "r"(a[2]), "r"(a[3]), "r"(b[0]), "r"(b[1]));
}

// ---------------- routing ---------------------------------------------------
__global__ void route_kernel(const int* __restrict__ ridx,
                             const float* __restrict__ rw) {
    __shared__ int cnt[E_], cur[E_], soff[E_ + 1];
    int t = threadIdx.x;
    if (t < E_) { cnt[t] = 0; cur[t] = 0; }
    __syncthreads();
    for (int i = t; i < NSLOT; i += blockDim.x)
        atomicAdd(&cnt[ridx[i]], 1);
    __syncthreads();
    if (t == 0) {
        int s = 0;
        for (int e = 0; e < E_; e++) { soff[e] = s; s += cnt[e]; }
        soff[E_] = s;
    }
    __syncthreads();
    for (int i = t; i < NSLOT; i += blockDim.x) {
        int e = ridx[i];
        int slot = soff[e] + atomicAdd(&cur[e], 1);
        d_slot_token[slot]  = i >> 1;
        d_slot_expert[slot] = e;
        d_slot_w[slot]      = rw[i];
    }
    if (t < E_) { d_count[t] = cnt[t]; d_off[t] = soff[t]; }
}

// ---------------- zero output ------------------------------------------------
__global__ void zero_out_kernel(float* __restrict__ out) {
    int i = blockIdx.x * 256 + threadIdx.x;
    *(float4*)&out[(size_t)i * 4] = make_float4(0.f, 0.f, 0.f, 0.f);
}

// ---------------- gather x rows -> f16 slot rows -----------------------------
__global__ void gather_xh_kernel(const float* __restrict__ x) {
    int slot = blockIdx.x;
    int tok  = d_slot_token[slot];
    int c    = threadIdx.x * 4;
    float4 v = __ldg((const float4*)&x[(size_t)tok * 1024 + c]);
    *(uint2*)&d_xh[(size_t)slot * 1024 + c] = cvt4h(v);
}

// ---------------- LoRA rank projection (f16 acts in, f16 r out) --------------
template <bool STAGE1>
__global__ void lora_r_kernel(const float* __restrict__ A) {  // [E,1024,16] fp32
    int slot = blockIdx.x;
    int e    = d_slot_expert[slot];
    const float* Ae = A + (size_t)e * 1024 * R_;
    const __half* srow = (STAGE1 ? d_xh : d_gh) + (size_t)slot * 1024;
    __half* rout = (STAGE1 ? d_r1 : d_r2) + (size_t)slot * R_;
    int tid = threadIdx.x;  // 256
    float acc[R_];
#pragma unroll
    for (int j = 0; j < R_; j++) acc[j] = 0.f;
    for (int k = tid; k < 1024; k += 256) {
        float a = __half2float(srow[k]);
        const float4* ar = (const float4*)(Ae + k * R_);
#pragma unroll
        for (int q = 0; q < 4; q++) {
            float4 v = __ldg(ar + q);
            acc[q * 4]     += a * v.x;
            acc[q * 4 + 1] += a * v.y;
            acc[q * 4 + 2] += a * v.z;
            acc[q * 4 + 3] += a * v.w;
        }
    }
#pragma unroll
    for (int o = 16; o > 0; o >>= 1)
#pragma unroll
        for (int j = 0; j < R_; j++)
            acc[j] += __shfl_down_sync(0xffffffffu, acc[j], o);
    __shared__ float wr[8][R_];
    int lane = tid & 31, w = tid >> 5;
    if (lane == 0)
#pragma unroll
        for (int j = 0; j < R_; j++) wr[w][j] = acc[j];
    __syncthreads();
    if (tid < R_) {
        float s = 0.f;
#pragma unroll
        for (int ww = 0; ww < 8; ww++) s += wr[ww][tid];
        rout[tid] = __float2half(s);   // SCALING = 1
    }
}

// SMEM (static 20480 B), double-buffered f16, BK=16:
//   A[stage]: 128 rows x 48B (32B data + 16B pad)  @ s*6144
//   B[stage]: 16 k-rows x 256B (XOR-swizzled)      @ 12288 + s*4096
#define SM_A(s) ((s) * 6144)
#define SM_B(s) (12288 + (s) * 4096)

// ================= grouped GEMM: f16-act + fp32-W stream, 2-phase pipeline ==
// STAGE1: d_gh = act(xh @ Wgu + r1 @ LBgu + bias)   Ncols=2048
// STAGE2: out += w * (gh @ Wdn + r2 @ LBdn + bias)  Ncols=1024, atomics
// CTA 128x128, 8 warps (2m x 4n), warp 64x32, BK=16, 65 K-iters (incl LoRA).
template <bool STAGE1>
__global__ __launch_bounds__(256, 2)
void moe_mma_kernel(const float* __restrict__ W,     // [E,1024,Ncols] fp32
                    const float* __restrict__ LB,    // [E,16,Ncols] fp32
                    const float* __restrict__ bias,  // [E,Ncols] fp32
                    float* __restrict__ Out,         // final out (stage2)
                    int Ncols) {
    const int e  = blockIdx.z;
    const int ne = d_count[e];
    const int off = d_off[e];
    const int n0  = blockIdx.x * 128;
    const __half* Ah = STAGE1 ? d_xh : d_gh;
    const __half* Rh = STAGE1 ? d_r1 : d_r2;

    __shared__ __align__(16) char sm[20480];
    const uint32_t sb = smem_u32(sm);

    const int tid  = threadIdx.x;
    const int lane = tid & 31;
    const int wid  = tid >> 5;
    const int wm   = wid >> 2;       // 0..1 (64 rows)
    const int wn   = wid & 3;        // 0..3 (32 cols)

    // per-thread load mapping
    const int arow = tid >> 1;            // A: 2 threads/row, 16B f16 each
    const int akh  = (tid & 1) * 8;       // half-chunk in halves
    const int krow = tid >> 4;            // B: 0..15
    const int bc   = tid & 15;            // 8-float (32B) group -> 16B f16 chunk
    const uint32_t a_st = arow * 48 + (tid & 1) * 16;
    const uint32_t b_st = krow * 256 + ((bc ^ (krow & 7)) << 4);
    const float* bptr  = W  + ((size_t)e * 1024 + krow) * Ncols + n0 + bc * 8;
    const float* lbptr = LB + ((size_t)e * R_   + krow) * Ncols + n0 + bc * 8;

    for (int mb = blockIdx.y; mb * 128 < ne; mb += 4) {
        const int m0 = mb * 128;
        const int aslot = off + m0 + arow;        // pad rows: valid mem, junk ok
        const __half* asrc = Ah + (size_t)aslot * 1024 + akh;
        const __half* rsrc = Rh + (size_t)aslot * R_ + akh;

        float acc[4][4][4];
#pragma unroll
        for (int i = 0; i < 4; i++)
#pragma unroll
            for (int j = 0; j < 4; j++)
#pragma unroll
                for (int q = 0; q < 4; q++) acc[i][j][q] = 0.f;

        // named pipeline registers (no runtime-indexed arrays -> no lmem)
        uint4  paA, paB;
        float4 pb0A, pb1A, pb0B, pb1B;
        auto ldA = [&](int t, uint4& pa) {
            if (t > 64) return;
            const __half* p = (t < 64) ? (asrc + t * 16) : rsrc;
            pa = __ldg((const uint4*)p);
        };
        auto ldB = [&](int t, float4& b0, float4& b1) {
            if (t > 64) return;
            const float* p = (t < 64) ? (bptr + (size_t)t * 16 * Ncols) : lbptr;
            b0 = __ldg((const float4*)p);
            b1 = __ldg((const float4*)(p + 4));
        };
        auto stTile = [&](int s, const uint4 pa, const float4 b0, const float4 b1) {
            *(uint4*)(sm + SM_A(s) + a_st) = pa;
            *(uint4*)(sm + SM_B(s) + b_st) = cvt8_f16(b0, b1);
        };
        auto mmaTile = [&](int s) {
            const uint32_t sA = sb + SM_A(s);
            const uint32_t sB = sb + SM_B(s);
            uint32_t bh[2][4];
            {
                int k = ((lane >> 3) & 1) * 8 + (lane & 7);
                int cbase = (lane >> 4);
#pragma unroll
                for (int g = 0; g < 2; g++) {
                    int c = wn * 4 + g * 2 + cbase;
                    ldsm4t(bh[g], sB + k * 256 + ((c ^ (k & 7)) << 4));
                }
            }
#pragma unroll
            for (int mt = 0; mt < 4; mt++) {
                uint32_t ah[4];
                int m = wm * 64 + mt * 16 + (lane & 15);
                ldsm4(ah, sA + m * 48 + (lane >> 4) * 16);
#pragma unroll
                for (int nt = 0; nt < 4; nt++)
                    mma16816f(acc[mt][nt], ah, &bh[nt >> 1][(nt & 1) * 2]);
            }
        };

        // ---- prologue: tiles 0,1 in regs; tile 0 staged ----
        ldA(0, paA); ldB(0, pb0A, pb1A);
        ldA(1, paB); ldB(1, pb0B, pb1B);
        stTile(0, paA, pb0A, pb1A);
        __syncthreads();

        // ---- main loop: 2-phase, tile t issued ~2 bodies before its STS ----
        for (int it = 0; it < 64; it += 2) {
            // phase 0: consume smem[0] = tile it
            ldA(it + 2, paA); ldB(it + 2, pb0A, pb1A);
            mmaTile(0);
            stTile(1, paB, pb0B, pb1B);      // tile it+1
            __syncthreads();
            // phase 1: consume smem[1] = tile it+1
            ldA(it + 3, paB); ldB(it + 3, pb0B, pb1B);
            mmaTile(1);
            stTile(0, paA, pb0A, pb1A);      // tile it+2
            __syncthreads();
        }
        mmaTile(0);                           // tile 64 (LoRA)

        // ---- epilogue ----
        const float* be = bias + (size_t)e * Ncols + n0;
        float bb[4][2];
#pragma unroll
        for (int nt = 0; nt < 4; nt++) {
            int col = wn * 32 + nt * 8 + (lane & 3) * 2;
            bb[nt][0] = __ldg(be + col);
            bb[nt][1] = __ldg(be + col + 1);
        }
#pragma unroll
        for (int mt = 0; mt < 4; mt++) {
            int rbase = m0 + wm * 64 + mt * 16 + (lane >> 2);
#pragma unroll
            for (int half = 0; half < 2; half++) {
                int r = rbase + half * 8;
                if (r >= ne) continue;
                int slot = off + r;
                if (STAGE1) {
                    __half* orow = d_gh + (size_t)slot * 1024 + (n0 >> 1);
#pragma unroll
                    for (int nt = 0; nt < 4; nt++) {
                        float c0 = acc[mt][nt][half * 2]     + bb[nt][0];
                        float c1 = acc[mt][nt][half * 2 + 1] + bb[nt][1];
                        int col = wn * 32 + nt * 8 + (lane & 3) * 2;
                        float gate = fminf(c0, LIMIT_);
                        float up   = fminf(fmaxf(c1, -LIMIT_), LIMIT_);
                        float glu  = gate / (1.f + expf(-ACT_ALPHA_ * gate));
                        orow[col >> 1] = __float2half((up + 1.f) * glu);
                    }
                } else {
                    float wgt = d_slot_w[slot];
                    size_t orow = (size_t)d_slot_token[slot] * 1024 + n0;
#pragma unroll
                    for (int nt = 0; nt < 4; nt++) {
                        float c0 = acc[mt][nt][half * 2]     + bb[nt][0];
                        float c1 = acc[mt][nt][half * 2 + 1] + bb[nt][1];
                        int col = wn * 32 + nt * 8 + (lane & 3) * 2;
                        atomicAdd(Out + orow + col,     wgt * c0);
                        atomicAdd(Out + orow + col + 1, wgt * c1);
                    }
                }
            }
        }
        __syncthreads();  // smem safe for next m-block
    }
}

// ---------------- launch: kernel launches ONLY ------------------------------
extern "C" void kernel_launch(void* const* d_in, const int* in_sizes, int n_in,
                              void* d_out, int out_size) {
    const float* x     = (const float*)d_in[0];
    const int*   ridx  = (const int*)  d_in[1];
    const float* rw    = (const float*)d_in[2];
    const float* w_gu  = (const float*)d_in[3];
    const float* b_gu  = (const float*)d_in[4];
    const float* w_dn  = (const float*)d_in[5];
    const float* b_dn  = (const float*)d_in[6];
    const float* la_gu = (const float*)d_in[7];
    const float* lb_gu = (const float*)d_in[8];
    const float* la_dn = (const float*)d_in[9];
    const float* lb_dn = (const float*)d_in[10];
    float* out = (float*)d_out;

    route_kernel<<<1, 1024>>>(ridx, rw);
    zero_out_kernel<<<T_ * H_ / 1024, 256>>>(out);
    gather_xh_kernel<<<NSLOT, 256>>>(x);

    lora_r_kernel<true ><<<NSLOT, 256>>>(la_gu);
    moe_mma_kernel<true ><<<dim3(D_ / 128, 4, E_), 256>>>(w_gu, lb_gu, b_gu,
                                                          nullptr, D_);
    lora_r_kernel<false><<<NSLOT, 256>>>(la_dn);
    moe_mma_kernel<false><<<dim3(H_ / 128, 4, E_), 256>>>(w_dn, lb_dn, b_dn,
                                                          out, H_);
}